// round 4
// baseline (speedup 1.0000x reference)
#include <cuda_runtime.h>

#define DINL __device__ __forceinline__

constexpr int V   = 32000;
constexpr int C   = 64;
constexpr int H   = 4;
constexpr int S   = 16;
constexpr int T   = 128;
constexpr int B   = 2;
constexpr int HID = 256;
constexpr int NPE = 4;
constexpr int BT  = B * T;     // 256
constexpr int D4  = 4 * C;     // 256

// ---------------- scratch (device globals; no malloc allowed) ----------------
__device__ float g_x   [BT * C];
__device__ float g_xn  [BT * C];
__device__ float g_pos [NPE * T * C];
__device__ float g_Qh  [H * B * T * D4];   // 0.5*(Qp + b1), [hb][t][d]
__device__ float g_KhT [H * B * D4 * T];   // 0.5*Kp, transposed [hb][d][t]
__device__ float g_v   [H * B * T * S];    // [hb][t][s]
__device__ float g_o   [BT * C];

DINL float sigmoidf_(float x) { return 1.0f / (1.0f + __expf(-x)); }

// block-wide sum over exactly 64 threads
DINL float bsum64(float v, float* sb, int tid) {
    sb[tid] = v; __syncthreads();
#pragma unroll
    for (int off = 32; off; off >>= 1) {
        if (tid < off) sb[tid] += sb[tid + off];
        __syncthreads();
    }
    float r = sb[0]; __syncthreads();
    return r;
}

// ---------------- K0: positional embeddings (4 tables, table->FFN->LN) -------
__global__ void k_pos(const float* __restrict__ tab,
                      const float* __restrict__ W1, const float* __restrict__ b1,
                      const float* __restrict__ W2, const float* __restrict__ b2,
                      const float* __restrict__ lg, const float* __restrict__ lb) {
    int p = blockIdx.x, t = blockIdx.y, c = threadIdx.x;
    __shared__ float pe[64], hh[64], sb[64];
    pe[c] = tab[(p * T + t) * C + c];
    __syncthreads();
    float a = b1[p * C + c];
    const float* w1 = W1 + p * C * C;
#pragma unroll 8
    for (int k = 0; k < C; k++) a = fmaf(pe[k], w1[k * C + c], a);
    hh[c] = sigmoidf_(a);
    __syncthreads();
    float y = b2[p * C + c];
    const float* w2 = W2 + p * C * C;
#pragma unroll 8
    for (int k = 0; k < C; k++) y = fmaf(hh[k], w2[k * C + c], y);
    float m = bsum64(y, sb, c) * (1.f / C);
    float d = y - m;
    float var = bsum64(d * d, sb, c) * (1.f / C);
    g_pos[(p * T + t) * C + c] = d * rsqrtf(var + 1e-5f) * lg[p * C + c] + lb[p * C + c];
}

// ---------------- token embedding gather -------------------------------------
__global__ void k_emb(const int* __restrict__ idx, const float* __restrict__ tok) {
    int row = blockIdx.x, c = threadIdx.x;
    g_x[row * C + c] = tok[idx[row] * C + c];
}

// ---------------- K1: ln1 + v projection --------------------------------------
__global__ void k_ln1v(const float* __restrict__ g1, const float* __restrict__ b1,
                       const float* __restrict__ valW) {
    int row = blockIdx.x, c = threadIdx.x;
    int b = row >> 7, t = row & 127;
    __shared__ float xs[64], sb[64];
    float x = g_x[row * C + c];
    float m = bsum64(x, sb, c) * (1.f / C);
    float d = x - m;
    float var = bsum64(d * d, sb, c) * (1.f / C);
    float xn = d * rsqrtf(var + 1e-5f) * g1[c] + b1[c];
    g_xn[row * C + c] = xn;
    xs[c] = xn;
    __syncthreads();
    int h = c >> 4, s = c & 15;
    float a = 0.f;
    const float* w = valW + h * C * S + s;
#pragma unroll 8
    for (int k = 0; k < C; k++) a = fmaf(xs[k], w[k * S], a);
    g_v[((h * B + b) * T + t) * S + s] = a;
}

// ---------------- K2: Q/K projections (pre-biased, pre-halved, K transposed) --
__global__ void k_qk(const float* __restrict__ W1, const float* __restrict__ b1, int p) {
    int hb = blockIdx.y;
    int h = hb >> 1, b = hb & 1;
    int t0 = blockIdx.x * 16;
    int d = threadIdx.x;  // 0..255
    __shared__ float x1T[128][17];      // [c][tt], padded
    __shared__ float ks[256 * 17];      // staging for transposed K write
    for (int idx = d; idx < 128 * 16; idx += 256) {
        int c = idx & 127, tt = idx >> 7;
        int t = t0 + tt;
        float v = (c < 64) ? g_pos[(p * T + t) * C + c]
                           : g_xn[(b * T + t) * C + (c - 64)];
        x1T[c][tt] = v;
    }
    __syncthreads();
    const float* Wk = W1 + h * D4 * D4;   // rows [0,128): key half
    const float* Wq = Wk + 128 * D4;      // rows [128,256): query half
    float ak[16], aq[16];
#pragma unroll
    for (int tt = 0; tt < 16; tt++) { ak[tt] = 0.f; aq[tt] = 0.f; }
    for (int c = 0; c < 128; c++) {
        float wk = Wk[c * D4 + d];
        float wq = Wq[c * D4 + d];
#pragma unroll
        for (int tt = 0; tt < 16; tt++) {
            float xv = x1T[c][tt];
            ak[tt] = fmaf(xv, wk, ak[tt]);
            aq[tt] = fmaf(xv, wq, aq[tt]);
        }
    }
    float bq = b1[h * D4 + d];
#pragma unroll
    for (int tt = 0; tt < 16; tt++) {
        g_Qh[(hb * T + t0 + tt) * D4 + d] = 0.5f * (aq[tt] + bq);
        ks[d * 17 + tt] = 0.5f * ak[tt];
    }
    __syncthreads();
    for (int idx = d; idx < 256 * 16; idx += 256) {
        int dd = idx >> 4, tt = idx & 15;
        g_KhT[(hb * D4 + dd) * T + t0 + tt] = ks[dd * 17 + tt];
    }
}

// ---------------- K3: scores (tanh trick) + softmax + o -----------------------
__global__ void k_attn(const float* __restrict__ W2a) {
    int i = blockIdx.x, hb = blockIdx.y;
    int h = hb >> 1, b = hb & 1;
    int j = threadIdx.x;  // 0..127
    __shared__ float Qrow[256], W2s[256], wei[128], rb[128];
    Qrow[j]       = g_Qh[(hb * T + i) * D4 + j];
    Qrow[128 + j] = g_Qh[(hb * T + i) * D4 + 128 + j];
    W2s[j]        = 0.5f * W2a[h * D4 + j];
    W2s[128 + j]  = 0.5f * W2a[h * D4 + 128 + j];
    __syncthreads();
    float sc = -1e30f;
    if (j <= i) {
        const float* Kc = g_KhT + hb * D4 * T + j;
        float acc = 0.f;
#pragma unroll 8
        for (int d = 0; d < D4; d++) {
            float tv = Qrow[d] + Kc[d * T];
            float th;
            asm("tanh.approx.f32 %0, %1;" : "=f"(th) : "f"(tv));
            acc = fmaf(W2s[d], th, acc);
        }
        sc = acc * 0.125f;  // C^-0.5; constant terms (b2, 0.5*sum(W2)) cancel in softmax
    }
    // softmax over j in [0, i]
    rb[j] = sc; __syncthreads();
#pragma unroll
    for (int off = 64; off; off >>= 1) {
        if (j < off) rb[j] = fmaxf(rb[j], rb[j + off]);
        __syncthreads();
    }
    float mx = rb[0]; __syncthreads();
    float w = (j <= i) ? __expf(sc - mx) : 0.f;
    rb[j] = w; __syncthreads();
#pragma unroll
    for (int off = 64; off; off >>= 1) {
        if (j < off) rb[j] += rb[j + off];
        __syncthreads();
    }
    float ssum = rb[0]; __syncthreads();
    wei[j] = w * __fdividef(1.f, ssum);
    __syncthreads();
    // o[i, h*16+s] = sum_j wei[j] * v[j][s]
    int so = j & 15, part = j >> 4;
    const float* vp = g_v + hb * T * S;
    float a = 0.f;
    for (int jj = part; jj <= i; jj += 8) a = fmaf(wei[jj], vp[jj * S + so], a);
    rb[j] = a; __syncthreads();
    if (j < 16) {
#pragma unroll
        for (int k = 1; k < 8; k++) a += rb[k * 16 + j];
        g_o[(b * T + i) * C + h * S + j] = a;
    }
}

// ---------------- K4: proj+residual, ln2, FFN+residual, ln3 -------------------
__global__ void k_mlp(const float* __restrict__ pW, const float* __restrict__ pb,
                      const float* __restrict__ g2, const float* __restrict__ b2,
                      const float* __restrict__ fW1, const float* __restrict__ fb1,
                      const float* __restrict__ fW2, const float* __restrict__ fb2,
                      const float* __restrict__ g3, const float* __restrict__ b3) {
    int row = blockIdx.x, c = threadIdx.x;
    __shared__ float orow[64], xn2s[64], hs[256], sb[64];
    orow[c] = g_o[row * C + c];
    __syncthreads();
    float xv = g_x[row * C + c] + pb[c];
#pragma unroll 8
    for (int k = 0; k < C; k++) xv = fmaf(orow[k], pW[k * C + c], xv);
    // ln2
    float m = bsum64(xv, sb, c) * (1.f / C);
    float d = xv - m;
    float var = bsum64(d * d, sb, c) * (1.f / C);
    float xn2 = d * rsqrtf(var + 1e-5f) * g2[c] + b2[c];
    xn2s[c] = xn2;
    __syncthreads();
#pragma unroll
    for (int mm = 0; mm < 4; mm++) {
        int jj = mm * 64 + c;
        float a = fb1[jj];
#pragma unroll 8
        for (int k = 0; k < C; k++) a = fmaf(xn2s[k], fW1[k * HID + jj], a);
        hs[jj] = sigmoidf_(a);
    }
    __syncthreads();
    float y = xv + fb2[c];
#pragma unroll 8
    for (int k = 0; k < HID; k++) y = fmaf(hs[k], fW2[k * C + c], y);
    // ln3 (block output)
    m = bsum64(y, sb, c) * (1.f / C);
    d = y - m;
    var = bsum64(d * d, sb, c) * (1.f / C);
    g_x[row * C + c] = d * rsqrtf(var + 1e-5f) * g3[c] + b3[c];
}

// ---------------- K5: lm_head [256,64]@[64,32000] -----------------------------
// Block: 32 rows x 256 vocab. 64 threads, 4 vocab (float4) each. x tile in smem.
__global__ void __launch_bounds__(64) k_lm(const float* __restrict__ W,
                                           const float* __restrict__ bias,
                                           float* __restrict__ out) {
    int vt = blockIdx.x, rt = blockIdx.y;
    int vv = vt * 256 + threadIdx.x * 4;
    __shared__ float xs[32][64];
    for (int idx = threadIdx.x; idx < 32 * 64; idx += 64) {
        int r = idx >> 6, cc = idx & 63;
        xs[r][cc] = g_x[(rt * 32 + r) * C + cc];
    }
    __syncthreads();
    float4 acc[32];
#pragma unroll
    for (int r = 0; r < 32; r++) acc[r] = make_float4(0.f, 0.f, 0.f, 0.f);
    for (int cb = 0; cb < 64; cb += 4) {
        const float4 w0 = *reinterpret_cast<const float4*>(W + (size_t)(cb + 0) * V + vv);
        const float4 w1 = *reinterpret_cast<const float4*>(W + (size_t)(cb + 1) * V + vv);
        const float4 w2 = *reinterpret_cast<const float4*>(W + (size_t)(cb + 2) * V + vv);
        const float4 w3 = *reinterpret_cast<const float4*>(W + (size_t)(cb + 3) * V + vv);
#pragma unroll
        for (int r = 0; r < 32; r++) {
            const float4 xq = *reinterpret_cast<const float4*>(&xs[r][cb]);
            acc[r].x += xq.x * w0.x + xq.y * w1.x + xq.z * w2.x + xq.w * w3.x;
            acc[r].y += xq.x * w0.y + xq.y * w1.y + xq.z * w2.y + xq.w * w3.y;
            acc[r].z += xq.x * w0.z + xq.y * w1.z + xq.z * w2.z + xq.w * w3.z;
            acc[r].w += xq.x * w0.w + xq.y * w1.w + xq.z * w2.w + xq.w * w3.w;
        }
    }
    float4 bb = *reinterpret_cast<const float4*>(bias + vv);
#pragma unroll
    for (int r = 0; r < 32; r++) {
        float4 a = acc[r];
        a.x += bb.x; a.y += bb.y; a.z += bb.z; a.w += bb.w;
        *reinterpret_cast<float4*>(out + (size_t)(rt * 32 + r) * V + vv) = a;
    }
}

// ---------------- launch -------------------------------------------------------
extern "C" void kernel_launch(void* const* d_in, const int* in_sizes, int n_in,
                              void* d_out, int out_size) {
    (void)in_sizes; (void)n_in; (void)out_size;
    const int*   idx      = (const int*)  d_in[0];
    const float* tok_emb  = (const float*)d_in[1];
    const float* pe_tab   = (const float*)d_in[2];
    const float* pe_W1    = (const float*)d_in[3];
    const float* pe_b1    = (const float*)d_in[4];
    const float* pe_W2    = (const float*)d_in[5];
    const float* pe_b2    = (const float*)d_in[6];
    const float* pe_lg    = (const float*)d_in[7];
    const float* pe_lb    = (const float*)d_in[8];
    const float* ln1_g    = (const float*)d_in[9];
    const float* ln1_b    = (const float*)d_in[10];
    const float* att_W1   = (const float*)d_in[11];
    const float* att_b1   = (const float*)d_in[12];
    const float* att_W2   = (const float*)d_in[13];
    /* att_b2 = d_in[14] — constant over j, cancels in softmax */
    const float* val_W    = (const float*)d_in[15];
    const float* proj_W   = (const float*)d_in[16];
    const float* proj_b   = (const float*)d_in[17];
    const float* ln2_g    = (const float*)d_in[18];
    const float* ln2_b    = (const float*)d_in[19];
    const float* ff_W1    = (const float*)d_in[20];
    const float* ff_b1    = (const float*)d_in[21];
    const float* ff_W2    = (const float*)d_in[22];
    const float* ff_b2    = (const float*)d_in[23];
    const float* ln3_g    = (const float*)d_in[24];
    const float* ln3_b    = (const float*)d_in[25];
    const float* lm_W     = (const float*)d_in[26];
    const float* lm_b     = (const float*)d_in[27];
    float* out = (float*)d_out;

    k_pos<<<dim3(NPE, T), 64>>>(pe_tab, pe_W1, pe_b1, pe_W2, pe_b2, pe_lg, pe_lb);
    k_emb<<<BT, 64>>>(idx, tok_emb);
    for (int p = 0; p < NPE; p++) {
        k_ln1v<<<BT, 64>>>(ln1_g, ln1_b, val_W);
        k_qk  <<<dim3(T / 16, H * B), 256>>>(att_W1, att_b1, p);
        k_attn<<<dim3(T, H * B), 128>>>(att_W2);
        k_mlp <<<BT, 64>>>(proj_W, proj_b, ln2_g, ln2_b,
                           ff_W1, ff_b1, ff_W2, ff_b2, ln3_g, ln3_b);
    }
    k_lm<<<dim3(V / 256, BT / 32), 64>>>(lm_W, lm_b, out);
}

// round 5
// speedup vs baseline: 1.2247x; 1.2247x over previous
#include <cuda_runtime.h>

#define DINL __device__ __forceinline__
typedef unsigned long long ull;

constexpr int V   = 32000;
constexpr int C   = 64;
constexpr int H   = 4;
constexpr int S   = 16;
constexpr int T   = 128;
constexpr int B   = 2;
constexpr int HID = 256;
constexpr int NPE = 4;
constexpr int BT  = B * T;     // 256
constexpr int D4  = 4 * C;     // 256

// ---------------- scratch (device globals; no malloc allowed) ----------------
__device__ float g_x   [BT * C];
__device__ float g_xn  [BT * C];
__device__ float g_pos [NPE * T * C];
__device__ float g_Qh  [H * B * T * D4];   // 0.5*(Qp + b1), [hb][t][d]
__device__ float g_KhT [H * B * D4 * T];   // 0.5*Kp, transposed [hb][d][t]
__device__ float g_v   [H * B * T * S];    // [hb][t][s]
__device__ float g_o   [BT * C];

DINL float sigmoidf_(float x) { return 1.0f / (1.0f + __expf(-x)); }

// packed f32x2 helpers (Blackwell: fma.rn.f32x2)
DINL ull fma2_(ull a, ull b, ull c) {
    ull r;
    asm("fma.rn.f32x2 %0, %1, %2, %3;" : "=l"(r) : "l"(a), "l"(b), "l"(c));
    return r;
}
DINL ull pack2_(float v) {
    ull r; unsigned u = __float_as_uint(v);
    asm("mov.b64 %0, {%1, %2};" : "=l"(r) : "r"(u), "r"(u));
    return r;
}
DINL void unpack2_(ull v, float& lo, float& hi) {
    unsigned a, b;
    asm("mov.b64 {%0, %1}, %2;" : "=r"(a), "=r"(b) : "l"(v));
    lo = __uint_as_float(a); hi = __uint_as_float(b);
}

// block-wide sum over exactly 64 threads
DINL float bsum64(float v, float* sb, int tid) {
    sb[tid] = v; __syncthreads();
#pragma unroll
    for (int off = 32; off; off >>= 1) {
        if (tid < off) sb[tid] += sb[tid + off];
        __syncthreads();
    }
    float r = sb[0]; __syncthreads();
    return r;
}

// ---------------- K0: positional embeddings (4 tables, table->FFN->LN) -------
__global__ void k_pos(const float* __restrict__ tab,
                      const float* __restrict__ W1, const float* __restrict__ b1,
                      const float* __restrict__ W2, const float* __restrict__ b2,
                      const float* __restrict__ lg, const float* __restrict__ lb) {
    int p = blockIdx.x, t = blockIdx.y, c = threadIdx.x;
    __shared__ float pe[64], hh[64], sb[64];
    pe[c] = tab[(p * T + t) * C + c];
    __syncthreads();
    float a = b1[p * C + c];
    const float* w1 = W1 + p * C * C;
#pragma unroll 8
    for (int k = 0; k < C; k++) a = fmaf(pe[k], w1[k * C + c], a);
    hh[c] = sigmoidf_(a);
    __syncthreads();
    float y = b2[p * C + c];
    const float* w2 = W2 + p * C * C;
#pragma unroll 8
    for (int k = 0; k < C; k++) y = fmaf(hh[k], w2[k * C + c], y);
    float m = bsum64(y, sb, c) * (1.f / C);
    float d = y - m;
    float var = bsum64(d * d, sb, c) * (1.f / C);
    g_pos[(p * T + t) * C + c] = d * rsqrtf(var + 1e-5f) * lg[p * C + c] + lb[p * C + c];
}

// ---------------- token embedding gather -------------------------------------
__global__ void k_emb(const int* __restrict__ idx, const float* __restrict__ tok) {
    int row = blockIdx.x, c = threadIdx.x;
    g_x[row * C + c] = tok[idx[row] * C + c];
}

// ---------------- K1: ln1 + v projection --------------------------------------
__global__ void k_ln1v(const float* __restrict__ g1, const float* __restrict__ b1,
                       const float* __restrict__ valW) {
    int row = blockIdx.x, c = threadIdx.x;
    int b = row >> 7, t = row & 127;
    __shared__ float xs[64], sb[64];
    float x = g_x[row * C + c];
    float m = bsum64(x, sb, c) * (1.f / C);
    float d = x - m;
    float var = bsum64(d * d, sb, c) * (1.f / C);
    float xn = d * rsqrtf(var + 1e-5f) * g1[c] + b1[c];
    g_xn[row * C + c] = xn;
    xs[c] = xn;
    __syncthreads();
    int h = c >> 4, s = c & 15;
    float a = 0.f;
    const float* w = valW + h * C * S + s;
#pragma unroll 8
    for (int k = 0; k < C; k++) a = fmaf(xs[k], w[k * S], a);
    g_v[((h * B + b) * T + t) * S + s] = a;
}

// ---------------- K2: Q/K projections, smem-staged weights, f32x2 over tt ----
// grid (T/16, H*B, 2 d-halves), block 128 (one thread per d within half)
__global__ void __launch_bounds__(128) k_qk(const float* __restrict__ W1,
                                            const float* __restrict__ b1, int p) {
    int dh = blockIdx.z;
    int hb = blockIdx.y;
    int h = hb >> 1, b = hb & 1;
    int t0 = blockIdx.x * 16;
    int tid = threadIdx.x;              // 0..127
    int d = dh * 128 + tid;

    __shared__ float xs[128][18];       // [c][tt], tt pairs 8B-aligned (18*4=72)
    __shared__ float wks[32][128];
    __shared__ float wqs[32][128];

    // load x1 tile: c<64 -> pos, c>=64 -> xn
    for (int idx = tid; idx < 128 * 16; idx += 128) {
        int c = idx & 127, tt = idx >> 7;
        int t = t0 + tt;
        xs[c][tt] = (c < 64) ? g_pos[(p * T + t) * C + c]
                             : g_xn[(b * T + t) * C + (c - 64)];
    }

    ull ak2[8], aq2[8];
    ull bq2 = pack2_(0.5f * b1[h * D4 + d]);
#pragma unroll
    for (int u = 0; u < 8; u++) { ak2[u] = 0ULL; aq2[u] = bq2; }

    const float* Wk = W1 + h * D4 * D4;         // rows [0,128): key half
    const float* Wq = Wk + 128 * D4;            // rows [128,256): query half
    int lg = tid >> 5, ls = tid & 31;           // cooperative-load mapping

    for (int c0 = 0; c0 < 128; c0 += 32) {
        __syncthreads();
#pragma unroll
        for (int rr = lg; rr < 32; rr += 4) {
            const float4 vk = *reinterpret_cast<const float4*>(
                &Wk[(c0 + rr) * D4 + dh * 128 + ls * 4]);
            *reinterpret_cast<float4*>(&wks[rr][ls * 4]) = vk;
            const float4 vq = *reinterpret_cast<const float4*>(
                &Wq[(c0 + rr) * D4 + dh * 128 + ls * 4]);
            *reinterpret_cast<float4*>(&wqs[rr][ls * 4]) = vq;
        }
        __syncthreads();
#pragma unroll 4
        for (int cc = 0; cc < 32; cc++) {
            ull wk2 = pack2_(0.5f * wks[cc][tid]);
            ull wq2 = pack2_(0.5f * wqs[cc][tid]);
            const ull* xp = reinterpret_cast<const ull*>(&xs[c0 + cc][0]);
#pragma unroll
            for (int u = 0; u < 8; u++) {
                ull xv = xp[u];
                ak2[u] = fma2_(xv, wk2, ak2[u]);
                aq2[u] = fma2_(xv, wq2, aq2[u]);
            }
        }
    }

    // K transposed: thread owns row d, writes 16 consecutive t as 8B pairs
    float* kout = &g_KhT[(hb * D4 + d) * T + t0];
#pragma unroll
    for (int u = 0; u < 8; u++)
        *reinterpret_cast<ull*>(&kout[2 * u]) = ak2[u];
    // Q: scatter per t
#pragma unroll
    for (int u = 0; u < 8; u++) {
        float lo, hi; unpack2_(aq2[u], lo, hi);
        g_Qh[(hb * T + t0 + 2 * u) * D4 + d]     = lo;
        g_Qh[(hb * T + t0 + 2 * u + 1) * D4 + d] = hi;
    }
}

// ---------------- K3: scores (tanh trick) + softmax + o -----------------------
__global__ void k_attn(const float* __restrict__ W2a) {
    int i = blockIdx.x, hb = blockIdx.y;
    int h = hb >> 1, b = hb & 1;
    int j = threadIdx.x;  // 0..127
    __shared__ float Qrow[256], W2s[256], wei[128], rb[128];
    Qrow[j]       = g_Qh[(hb * T + i) * D4 + j];
    Qrow[128 + j] = g_Qh[(hb * T + i) * D4 + 128 + j];
    W2s[j]        = 0.5f * W2a[h * D4 + j];
    W2s[128 + j]  = 0.5f * W2a[h * D4 + 128 + j];
    __syncthreads();
    float sc = -1e30f;
    if (j <= i) {
        const float* Kc = g_KhT + hb * D4 * T + j;
        float acc = 0.f;
#pragma unroll 8
        for (int d = 0; d < D4; d++) {
            float tv = Qrow[d] + Kc[d * T];
            float th;
            asm("tanh.approx.f32 %0, %1;" : "=f"(th) : "f"(tv));
            acc = fmaf(W2s[d], th, acc);
        }
        sc = acc * 0.125f;  // C^-0.5; constant terms (b2, 0.5*sum(W2)) cancel in softmax
    }
    // softmax over j in [0, i]
    rb[j] = sc; __syncthreads();
#pragma unroll
    for (int off = 64; off; off >>= 1) {
        if (j < off) rb[j] = fmaxf(rb[j], rb[j + off]);
        __syncthreads();
    }
    float mx = rb[0]; __syncthreads();
    float w = (j <= i) ? __expf(sc - mx) : 0.f;
    rb[j] = w; __syncthreads();
#pragma unroll
    for (int off = 64; off; off >>= 1) {
        if (j < off) rb[j] += rb[j + off];
        __syncthreads();
    }
    float ssum = rb[0]; __syncthreads();
    wei[j] = w * __fdividef(1.f, ssum);
    __syncthreads();
    // o[i, h*16+s] = sum_j wei[j] * v[j][s]
    int so = j & 15, part = j >> 4;
    const float* vp = g_v + hb * T * S;
    float a = 0.f;
    for (int jj = part; jj <= i; jj += 8) a = fmaf(wei[jj], vp[jj * S + so], a);
    rb[j] = a; __syncthreads();
    if (j < 16) {
#pragma unroll
        for (int k = 1; k < 8; k++) a += rb[k * 16 + j];
        g_o[(b * T + i) * C + h * S + j] = a;
    }
}

// ---------------- K4: proj+residual, ln2, FFN+residual, ln3 -------------------
__global__ void k_mlp(const float* __restrict__ pW, const float* __restrict__ pb,
                      const float* __restrict__ g2, const float* __restrict__ b2,
                      const float* __restrict__ fW1, const float* __restrict__ fb1,
                      const float* __restrict__ fW2, const float* __restrict__ fb2,
                      const float* __restrict__ g3, const float* __restrict__ b3) {
    int row = blockIdx.x, c = threadIdx.x;
    __shared__ float orow[64], xn2s[64], hs[256], sb[64];
    orow[c] = g_o[row * C + c];
    __syncthreads();
    float xv = g_x[row * C + c] + pb[c];
#pragma unroll 8
    for (int k = 0; k < C; k++) xv = fmaf(orow[k], pW[k * C + c], xv);
    // ln2
    float m = bsum64(xv, sb, c) * (1.f / C);
    float d = xv - m;
    float var = bsum64(d * d, sb, c) * (1.f / C);
    float xn2 = d * rsqrtf(var + 1e-5f) * g2[c] + b2[c];
    xn2s[c] = xn2;
    __syncthreads();
#pragma unroll
    for (int mm = 0; mm < 4; mm++) {
        int jj = mm * 64 + c;
        float a = fb1[jj];
#pragma unroll 8
        for (int k = 0; k < C; k++) a = fmaf(xn2s[k], fW1[k * HID + jj], a);
        hs[jj] = sigmoidf_(a);
    }
    __syncthreads();
    float y = xv + fb2[c];
#pragma unroll 8
    for (int k = 0; k < HID; k++) y = fmaf(hs[k], fW2[k * C + c], y);
    // ln3 (block output)
    m = bsum64(y, sb, c) * (1.f / C);
    d = y - m;
    var = bsum64(d * d, sb, c) * (1.f / C);
    g_x[row * C + c] = d * rsqrtf(var + 1e-5f) * g3[c] + b3[c];
}

// ---------------- K5: lm_head [256,64]@[64,32000], f32x2 over vocab pairs -----
// Block: 32 rows x 256 vocab tile. 128 threads, each owns 1 vocab pair (ull acc).
__global__ void __launch_bounds__(128) k_lm(const float* __restrict__ W,
                                            const float* __restrict__ bias,
                                            float* __restrict__ out) {
    int vt = blockIdx.x, rt = blockIdx.y;
    int vvg = vt * 256 + threadIdx.x * 2;
    __shared__ alignas(16) float xs[32][68];
    for (int idx = threadIdx.x; idx < 32 * 64; idx += 128) {
        int r = idx >> 6, cc = idx & 63;
        xs[r][cc] = g_x[(rt * 32 + r) * C + cc];
    }
    ull bb = *reinterpret_cast<const ull*>(bias + vvg);
    ull acc[32];
#pragma unroll
    for (int r = 0; r < 32; r++) acc[r] = bb;
    __syncthreads();
    for (int cb = 0; cb < 64; cb += 4) {
        const ull w0 = *reinterpret_cast<const ull*>(W + (size_t)(cb + 0) * V + vvg);
        const ull w1 = *reinterpret_cast<const ull*>(W + (size_t)(cb + 1) * V + vvg);
        const ull w2 = *reinterpret_cast<const ull*>(W + (size_t)(cb + 2) * V + vvg);
        const ull w3 = *reinterpret_cast<const ull*>(W + (size_t)(cb + 3) * V + vvg);
#pragma unroll
        for (int r = 0; r < 32; r++) {
            const float4 xq = *reinterpret_cast<const float4*>(&xs[r][cb]);
            acc[r] = fma2_(w0, pack2_(xq.x), acc[r]);
            acc[r] = fma2_(w1, pack2_(xq.y), acc[r]);
            acc[r] = fma2_(w2, pack2_(xq.z), acc[r]);
            acc[r] = fma2_(w3, pack2_(xq.w), acc[r]);
        }
    }
#pragma unroll
    for (int r = 0; r < 32; r++)
        *reinterpret_cast<ull*>(out + (size_t)(rt * 32 + r) * V + vvg) = acc[r];
}

// ---------------- launch -------------------------------------------------------
extern "C" void kernel_launch(void* const* d_in, const int* in_sizes, int n_in,
                              void* d_out, int out_size) {
    (void)in_sizes; (void)n_in; (void)out_size;
    const int*   idx      = (const int*)  d_in[0];
    const float* tok_emb  = (const float*)d_in[1];
    const float* pe_tab   = (const float*)d_in[2];
    const float* pe_W1    = (const float*)d_in[3];
    const float* pe_b1    = (const float*)d_in[4];
    const float* pe_W2    = (const float*)d_in[5];
    const float* pe_b2    = (const float*)d_in[6];
    const float* pe_lg    = (const float*)d_in[7];
    const float* pe_lb    = (const float*)d_in[8];
    const float* ln1_g    = (const float*)d_in[9];
    const float* ln1_b    = (const float*)d_in[10];
    const float* att_W1   = (const float*)d_in[11];
    const float* att_b1   = (const float*)d_in[12];
    const float* att_W2   = (const float*)d_in[13];
    /* att_b2 = d_in[14] — constant over j, cancels in softmax */
    const float* val_W    = (const float*)d_in[15];
    const float* proj_W   = (const float*)d_in[16];
    const float* proj_b   = (const float*)d_in[17];
    const float* ln2_g    = (const float*)d_in[18];
    const float* ln2_b    = (const float*)d_in[19];
    const float* ff_W1    = (const float*)d_in[20];
    const float* ff_b1    = (const float*)d_in[21];
    const float* ff_W2    = (const float*)d_in[22];
    const float* ff_b2    = (const float*)d_in[23];
    const float* ln3_g    = (const float*)d_in[24];
    const float* ln3_b    = (const float*)d_in[25];
    const float* lm_W     = (const float*)d_in[26];
    const float* lm_b     = (const float*)d_in[27];
    float* out = (float*)d_out;

    k_pos<<<dim3(NPE, T), 64>>>(pe_tab, pe_W1, pe_b1, pe_W2, pe_b2, pe_lg, pe_lb);
    k_emb<<<BT, 64>>>(idx, tok_emb);
    for (int p = 0; p < NPE; p++) {
        k_ln1v<<<BT, 64>>>(ln1_g, ln1_b, val_W);
        k_qk  <<<dim3(T / 16, H * B, 2), 128>>>(att_W1, att_b1, p);
        k_attn<<<dim3(T, H * B), 128>>>(att_W2);
        k_mlp <<<BT, 64>>>(proj_W, proj_b, ln2_g, ln2_b,
                           ff_W1, ff_b1, ff_W2, ff_b2, ln3_g, ln3_b);
    }
    k_lm<<<dim3(V / 256, BT / 32), 128>>>(lm_W, lm_b, out);
}

// round 6
// speedup vs baseline: 1.2268x; 1.0017x over previous
#include <cuda_runtime.h>

#define DINL __device__ __forceinline__
typedef unsigned long long ull;
#define FULLM 0xffffffffu

constexpr int V   = 32000;
constexpr int C   = 64;
constexpr int H   = 4;
constexpr int S   = 16;
constexpr int T   = 128;
constexpr int B   = 2;
constexpr int HID = 256;
constexpr int NPE = 4;
constexpr int BT  = B * T;     // 256
constexpr int D4  = 4 * C;     // 256

// ---------------- scratch (device globals; no malloc allowed) ----------------
__device__ float g_x   [BT * C];
__device__ float g_xn  [BT * C];
__device__ float g_pos [NPE * T * C];
__device__ float g_Qh  [H * B * T * D4];   // 0.5*(Qp + b1), [hb][t][d]
__device__ float g_KhT [H * B * D4 * T];   // 0.5*Kp, transposed [hb][d][t]
__device__ float g_v   [H * B * T * S];    // [hb][t][s]
__device__ float g_o   [BT * C];

DINL float sigmoidf_(float x) { return 1.0f / (1.0f + __expf(-x)); }

// packed f32x2 helpers (Blackwell: fma.rn.f32x2)
DINL ull fma2_(ull a, ull b, ull c) {
    ull r;
    asm("fma.rn.f32x2 %0, %1, %2, %3;" : "=l"(r) : "l"(a), "l"(b), "l"(c));
    return r;
}
DINL ull pack2_(float v) {
    ull r; unsigned u = __float_as_uint(v);
    asm("mov.b64 %0, {%1, %2};" : "=l"(r) : "r"(u), "r"(u));
    return r;
}
DINL ull packlh_(float lo, float hi) {
    ull r;
    asm("mov.b64 %0, {%1, %2};" : "=l"(r) : "r"(__float_as_uint(lo)), "r"(__float_as_uint(hi)));
    return r;
}
DINL void unpack2_(ull v, float& lo, float& hi) {
    unsigned a, b;
    asm("mov.b64 {%0, %1}, %2;" : "=r"(a), "=r"(b) : "l"(v));
    lo = __uint_as_float(a); hi = __uint_as_float(b);
}
DINL float wsum32_(float v) {
#pragma unroll
    for (int off = 16; off; off >>= 1) v += __shfl_xor_sync(FULLM, v, off);
    return v;
}

// block-wide sum over exactly 64 threads
DINL float bsum64(float v, float* sb, int tid) {
    sb[tid] = v; __syncthreads();
#pragma unroll
    for (int off = 32; off; off >>= 1) {
        if (tid < off) sb[tid] += sb[tid + off];
        __syncthreads();
    }
    float r = sb[0]; __syncthreads();
    return r;
}

// ---------------- K0: positional embeddings (4 tables, table->FFN->LN) -------
__global__ void k_pos(const float* __restrict__ tab,
                      const float* __restrict__ W1, const float* __restrict__ b1,
                      const float* __restrict__ W2, const float* __restrict__ b2,
                      const float* __restrict__ lg, const float* __restrict__ lb) {
    int p = blockIdx.x, t = blockIdx.y, c = threadIdx.x;
    __shared__ float pe[64], hh[64], sb[64];
    pe[c] = tab[(p * T + t) * C + c];
    __syncthreads();
    float a = b1[p * C + c];
    const float* w1 = W1 + p * C * C;
#pragma unroll 8
    for (int k = 0; k < C; k++) a = fmaf(pe[k], w1[k * C + c], a);
    hh[c] = sigmoidf_(a);
    __syncthreads();
    float y = b2[p * C + c];
    const float* w2 = W2 + p * C * C;
#pragma unroll 8
    for (int k = 0; k < C; k++) y = fmaf(hh[k], w2[k * C + c], y);
    float m = bsum64(y, sb, c) * (1.f / C);
    float d = y - m;
    float var = bsum64(d * d, sb, c) * (1.f / C);
    g_pos[(p * T + t) * C + c] = d * rsqrtf(var + 1e-5f) * lg[p * C + c] + lb[p * C + c];
}

// ---------------- token embedding gather -------------------------------------
__global__ void k_emb(const int* __restrict__ idx, const float* __restrict__ tok) {
    int row = blockIdx.x, c = threadIdx.x;
    g_x[row * C + c] = tok[idx[row] * C + c];
}

// ---------------- K1: ln1 + v projection (first iteration only) ---------------
__global__ void k_ln1v(const float* __restrict__ g1, const float* __restrict__ b1,
                       const float* __restrict__ valW) {
    int row = blockIdx.x, c = threadIdx.x;
    int b = row >> 7, t = row & 127;
    __shared__ float xs[64], sb[64];
    float x = g_x[row * C + c];
    float m = bsum64(x, sb, c) * (1.f / C);
    float d = x - m;
    float var = bsum64(d * d, sb, c) * (1.f / C);
    float xn = d * rsqrtf(var + 1e-5f) * g1[c] + b1[c];
    g_xn[row * C + c] = xn;
    xs[c] = xn;
    __syncthreads();
    int h = c >> 4, s = c & 15;
    float a = 0.f;
    const float* w = valW + h * C * S + s;
#pragma unroll 8
    for (int k = 0; k < C; k++) a = fmaf(xs[k], w[k * S], a);
    g_v[((h * B + b) * T + t) * S + s] = a;
}

// ---------------- K2: Q/K projections, direct-L2 weights, f32x2 over tokens --
// grid (T/8, H*B, 2 d-halves), block 128 (one thread per d within half)
__global__ void __launch_bounds__(128) k_qk(const float* __restrict__ W1,
                                            const float* __restrict__ b1, int p) {
    int dh = blockIdx.z;
    int hb = blockIdx.y;
    int h = hb >> 1, b = hb & 1;
    int t0 = blockIdx.x * 8;
    int tid = threadIdx.x;              // 0..127
    int d = dh * 128 + tid;

    __shared__ float xs[128][10];       // [c][tt], 8 tokens, 8B-aligned rows

    for (int idx = tid; idx < 128 * 8; idx += 128) {
        int c = idx & 127, tt = idx >> 7;
        int t = t0 + tt;
        xs[c][tt] = (c < 64) ? g_pos[(p * T + t) * C + c]
                             : g_xn[(b * T + t) * C + (c - 64)];
    }
    __syncthreads();

    ull ak2[4], aq2[4];
    ull bq2 = pack2_(0.5f * b1[h * D4 + d]);
#pragma unroll
    for (int u = 0; u < 4; u++) { ak2[u] = 0ULL; aq2[u] = bq2; }

    const float* Wk = W1 + h * D4 * D4 + d;   // rows [0,128): key half
    const float* Wq = Wk + 128 * D4;          // rows [128,256): query half

#pragma unroll 8
    for (int c = 0; c < 128; c++) {
        ull wk2 = pack2_(0.5f * Wk[c * D4]);
        ull wq2 = pack2_(0.5f * Wq[c * D4]);
        const ull* xp = reinterpret_cast<const ull*>(&xs[c][0]);
#pragma unroll
        for (int u = 0; u < 4; u++) {
            ull xv = xp[u];
            ak2[u] = fma2_(xv, wk2, ak2[u]);
            aq2[u] = fma2_(xv, wq2, aq2[u]);
        }
    }

    // K transposed: thread owns row d, writes 8 consecutive t as 8B pairs
    float* kout = &g_KhT[(hb * D4 + d) * T + t0];
#pragma unroll
    for (int u = 0; u < 4; u++)
        *reinterpret_cast<ull*>(&kout[2 * u]) = ak2[u];
    // Q: scatter per t (coalesced across tid)
#pragma unroll
    for (int u = 0; u < 4; u++) {
        float lo, hi; unpack2_(aq2[u], lo, hi);
        g_Qh[(hb * T + t0 + 2 * u) * D4 + d]     = lo;
        g_Qh[(hb * T + t0 + 2 * u + 1) * D4 + d] = hi;
    }
}

// ---------------- K3: scores (tanh trick) + softmax + o -----------------------
__global__ void k_attn(const float* __restrict__ W2a) {
    int i = blockIdx.x, hb = blockIdx.y;
    int h = hb >> 1, b = hb & 1;
    int j = threadIdx.x;  // 0..127
    __shared__ float2 qw[256];
    __shared__ float wei[128], rb[128];
    qw[j]       = make_float2(g_Qh[(hb * T + i) * D4 + j],
                              0.5f * W2a[h * D4 + j]);
    qw[128 + j] = make_float2(g_Qh[(hb * T + i) * D4 + 128 + j],
                              0.5f * W2a[h * D4 + 128 + j]);
    __syncthreads();
    float sc = -1e30f;
    if (j <= i) {
        const float* Kc = g_KhT + hb * D4 * T + j;
        float acc = 0.f;
#pragma unroll 8
        for (int d = 0; d < D4; d++) {
            float2 q = qw[d];
            float tv = q.x + Kc[d * T];
            float th;
            asm("tanh.approx.f32 %0, %1;" : "=f"(th) : "f"(tv));
            acc = fmaf(q.y, th, acc);
        }
        sc = acc * 0.125f;  // C^-0.5; constant terms cancel in softmax
    }
    // softmax over j in [0, i]
    rb[j] = sc; __syncthreads();
#pragma unroll
    for (int off = 64; off; off >>= 1) {
        if (j < off) rb[j] = fmaxf(rb[j], rb[j + off]);
        __syncthreads();
    }
    float mx = rb[0]; __syncthreads();
    float w = (j <= i) ? __expf(sc - mx) : 0.f;
    rb[j] = w; __syncthreads();
#pragma unroll
    for (int off = 64; off; off >>= 1) {
        if (j < off) rb[j] += rb[j + off];
        __syncthreads();
    }
    float ssum = rb[0]; __syncthreads();
    wei[j] = w * __fdividef(1.f, ssum);
    __syncthreads();
    // o[i, h*16+s] = sum_j wei[j] * v[j][s]
    int so = j & 15, part = j >> 4;
    const float* vp = g_v + hb * T * S;
    float a = 0.f;
    for (int jj = part; jj <= i; jj += 8) a = fmaf(wei[jj], vp[jj * S + so], a);
    rb[j] = a; __syncthreads();
    if (j < 16) {
#pragma unroll
        for (int k = 1; k < 8; k++) a += rb[k * 16 + j];
        g_o[(b * T + i) * C + h * S + j] = a;
    }
}

// ---------------- K4: warp-per-row proj+ln2+FFN+ln3, fused ln1+v --------------
// grid(BT/2) x 64 threads: each warp owns one row; no __syncthreads.
__global__ void __launch_bounds__(64) k_mlp(
        const float* __restrict__ pW, const float* __restrict__ pb,
        const float* __restrict__ g2, const float* __restrict__ b2,
        const float* __restrict__ fW1, const float* __restrict__ fb1,
        const float* __restrict__ fW2, const float* __restrict__ fb2,
        const float* __restrict__ g3, const float* __restrict__ b3,
        const float* __restrict__ g1, const float* __restrict__ b1,
        const float* __restrict__ valW) {
    int w = threadIdx.x >> 5, lam = threadIdx.x & 31;
    int row = blockIdx.x * 2 + w;
    int b = row >> 7, t = row & 127;
    __shared__ ull hs2[2][256];

    float2 o2 = reinterpret_cast<const float2*>(g_o)[row * 32 + lam];
    float2 x2 = reinterpret_cast<const float2*>(g_x)[row * 32 + lam];
    float2 pb2 = reinterpret_cast<const float2*>(pb)[lam];

    // proj + residual: acc = x + pb + o @ pW
    ull acc = packlh_(x2.x + pb2.x, x2.y + pb2.y);
    const ull* pW2 = reinterpret_cast<const ull*>(pW);
#pragma unroll 4
    for (int kp = 0; kp < 32; kp++) {
        float ox = __shfl_sync(FULLM, o2.x, kp);
        float oy = __shfl_sync(FULLM, o2.y, kp);
        ull w0 = pW2[(2 * kp) * 32 + lam];
        ull w1 = pW2[(2 * kp + 1) * 32 + lam];
        acc = fma2_(pack2_(ox), w0, acc);
        acc = fma2_(pack2_(oy), w1, acc);
    }
    float xv0, xv1; unpack2_(acc, xv0, xv1);

    // ln2
    float m = wsum32_(xv0 + xv1) * (1.f / C);
    float d0 = xv0 - m, d1 = xv1 - m;
    float var = wsum32_(d0 * d0 + d1 * d1) * (1.f / C);
    float rstd = rsqrtf(var + 1e-5f);
    float2 g2v = reinterpret_cast<const float2*>(g2)[lam];
    float2 b2v = reinterpret_cast<const float2*>(b2)[lam];
    float xn0 = d0 * rstd * g2v.x + b2v.x;
    float xn1 = d1 * rstd * g2v.y + b2v.y;

    // FFN1: lane owns hid [8*lam, 8*lam+8)
    ull a4[4];
    const ull* fb1u = reinterpret_cast<const ull*>(fb1);
#pragma unroll
    for (int u = 0; u < 4; u++) a4[u] = fb1u[lam * 4 + u];
#pragma unroll 4
    for (int kp = 0; kp < 32; kp++) {
        float k0v = __shfl_sync(FULLM, xn0, kp);
        float k1v = __shfl_sync(FULLM, xn1, kp);
        const ull* r0 = reinterpret_cast<const ull*>(fW1 + (2 * kp) * HID) + lam * 4;
        const ull* r1 = r0 + HID / 2;
        ull p0 = pack2_(k0v), p1 = pack2_(k1v);
#pragma unroll
        for (int u = 0; u < 4; u++) {
            a4[u] = fma2_(p0, r0[u], a4[u]);
            a4[u] = fma2_(p1, r1[u], a4[u]);
        }
    }
#pragma unroll
    for (int u = 0; u < 4; u++) {
        float lo, hi; unpack2_(a4[u], lo, hi);
        hs2[w][8 * lam + 2 * u]     = pack2_(sigmoidf_(lo));
        hs2[w][8 * lam + 2 * u + 1] = pack2_(sigmoidf_(hi));
    }
    __syncwarp();

    // FFN2 + residual
    float2 fb2v = reinterpret_cast<const float2*>(fb2)[lam];
    ull accy = packlh_(xv0 + fb2v.x, xv1 + fb2v.y);
    const ull* fW2u = reinterpret_cast<const ull*>(fW2);
#pragma unroll 8
    for (int k = 0; k < HID; k++)
        accy = fma2_(hs2[w][k], fW2u[k * 32 + lam], accy);
    float y0, y1; unpack2_(accy, y0, y1);

    // ln3 -> block output
    m = wsum32_(y0 + y1) * (1.f / C);
    d0 = y0 - m; d1 = y1 - m;
    var = wsum32_(d0 * d0 + d1 * d1) * (1.f / C);
    rstd = rsqrtf(var + 1e-5f);
    float2 g3v = reinterpret_cast<const float2*>(g3)[lam];
    float2 b3v = reinterpret_cast<const float2*>(b3)[lam];
    float z0 = d0 * rstd * g3v.x + b3v.x;
    float z1 = d1 * rstd * g3v.y + b3v.y;
    reinterpret_cast<float2*>(g_x)[row * 32 + lam] = make_float2(z0, z1);

    // fused ln1 for next layer
    m = wsum32_(z0 + z1) * (1.f / C);
    d0 = z0 - m; d1 = z1 - m;
    var = wsum32_(d0 * d0 + d1 * d1) * (1.f / C);
    rstd = rsqrtf(var + 1e-5f);
    float2 g1v = reinterpret_cast<const float2*>(g1)[lam];
    float2 b1v = reinterpret_cast<const float2*>(b1)[lam];
    float q0 = d0 * rstd * g1v.x + b1v.x;
    float q1 = d1 * rstd * g1v.y + b1v.y;
    reinterpret_cast<float2*>(g_xn)[row * 32 + lam] = make_float2(q0, q1);

    // fused v projection: lane owns out pair c=(2lam, 2lam+1) -> h=lam>>3, s0=(2lam)&15
    int hv = lam >> 3, sp = lam & 7;
    const ull* vwb = reinterpret_cast<const ull*>(valW) + hv * 512 + sp;
    ull accv = 0ULL;
#pragma unroll 4
    for (int kp = 0; kp < 32; kp++) {
        float k0v = __shfl_sync(FULLM, q0, kp);
        float k1v = __shfl_sync(FULLM, q1, kp);
        ull w0 = vwb[kp * 16];
        ull w1 = vwb[kp * 16 + 8];
        accv = fma2_(pack2_(k0v), w0, accv);
        accv = fma2_(pack2_(k1v), w1, accv);
    }
    reinterpret_cast<ull*>(g_v)[((hv * B + b) * T + t) * 8 + sp] = accv;
}

// ---------------- K5: lm_head, 4 vocab/thread, f32x2 --------------------------
// grid (V/256, BT/32), block 64; thread owns 2 vocab pairs, 32 rows.
__global__ void __launch_bounds__(64) k_lm(const float* __restrict__ W,
                                           const float* __restrict__ bias,
                                           float* __restrict__ out) {
    int vt = blockIdx.x, rt = blockIdx.y;
    int vv = vt * 256 + threadIdx.x * 4;
    __shared__ alignas(16) float xs[32][68];
    for (int idx = threadIdx.x; idx < 32 * 64; idx += 64) {
        int r = idx >> 6, cc = idx & 63;
        xs[r][cc] = g_x[(rt * 32 + r) * C + cc];
    }
    ulonglong2 bb = *reinterpret_cast<const ulonglong2*>(bias + vv);
    ull acc[32][2];
#pragma unroll
    for (int r = 0; r < 32; r++) { acc[r][0] = bb.x; acc[r][1] = bb.y; }
    __syncthreads();
    for (int cb = 0; cb < 64; cb += 4) {
        const ulonglong2 w0 = *reinterpret_cast<const ulonglong2*>(W + (size_t)(cb + 0) * V + vv);
        const ulonglong2 w1 = *reinterpret_cast<const ulonglong2*>(W + (size_t)(cb + 1) * V + vv);
        const ulonglong2 w2 = *reinterpret_cast<const ulonglong2*>(W + (size_t)(cb + 2) * V + vv);
        const ulonglong2 w3 = *reinterpret_cast<const ulonglong2*>(W + (size_t)(cb + 3) * V + vv);
#pragma unroll
        for (int r = 0; r < 32; r++) {
            const float4 xq = *reinterpret_cast<const float4*>(&xs[r][cb]);
            ull px;
            px = pack2_(xq.x); acc[r][0] = fma2_(w0.x, px, acc[r][0]); acc[r][1] = fma2_(w0.y, px, acc[r][1]);
            px = pack2_(xq.y); acc[r][0] = fma2_(w1.x, px, acc[r][0]); acc[r][1] = fma2_(w1.y, px, acc[r][1]);
            px = pack2_(xq.z); acc[r][0] = fma2_(w2.x, px, acc[r][0]); acc[r][1] = fma2_(w2.y, px, acc[r][1]);
            px = pack2_(xq.w); acc[r][0] = fma2_(w3.x, px, acc[r][0]); acc[r][1] = fma2_(w3.y, px, acc[r][1]);
        }
    }
#pragma unroll
    for (int r = 0; r < 32; r++) {
        ulonglong2 o2; o2.x = acc[r][0]; o2.y = acc[r][1];
        *reinterpret_cast<ulonglong2*>(out + (size_t)(rt * 32 + r) * V + vv) = o2;
    }
}

// ---------------- launch -------------------------------------------------------
extern "C" void kernel_launch(void* const* d_in, const int* in_sizes, int n_in,
                              void* d_out, int out_size) {
    (void)in_sizes; (void)n_in; (void)out_size;
    const int*   idx      = (const int*)  d_in[0];
    const float* tok_emb  = (const float*)d_in[1];
    const float* pe_tab   = (const float*)d_in[2];
    const float* pe_W1    = (const float*)d_in[3];
    const float* pe_b1    = (const float*)d_in[4];
    const float* pe_W2    = (const float*)d_in[5];
    const float* pe_b2    = (const float*)d_in[6];
    const float* pe_lg    = (const float*)d_in[7];
    const float* pe_lb    = (const float*)d_in[8];
    const float* ln1_g    = (const float*)d_in[9];
    const float* ln1_b    = (const float*)d_in[10];
    const float* att_W1   = (const float*)d_in[11];
    const float* att_b1   = (const float*)d_in[12];
    const float* att_W2   = (const float*)d_in[13];
    /* att_b2 = d_in[14] — constant over j, cancels in softmax */
    const float* val_W    = (const float*)d_in[15];
    const float* proj_W   = (const float*)d_in[16];
    const float* proj_b   = (const float*)d_in[17];
    const float* ln2_g    = (const float*)d_in[18];
    const float* ln2_b    = (const float*)d_in[19];
    const float* ff_W1    = (const float*)d_in[20];
    const float* ff_b1    = (const float*)d_in[21];
    const float* ff_W2    = (const float*)d_in[22];
    const float* ff_b2    = (const float*)d_in[23];
    const float* ln3_g    = (const float*)d_in[24];
    const float* ln3_b    = (const float*)d_in[25];
    const float* lm_W     = (const float*)d_in[26];
    const float* lm_b     = (const float*)d_in[27];
    float* out = (float*)d_out;

    k_pos<<<dim3(NPE, T), 64>>>(pe_tab, pe_W1, pe_b1, pe_W2, pe_b2, pe_lg, pe_lb);
    k_emb<<<BT, 64>>>(idx, tok_emb);
    k_ln1v<<<BT, 64>>>(ln1_g, ln1_b, val_W);
    for (int p = 0; p < NPE; p++) {
        k_qk  <<<dim3(T / 8, H * B, 2), 128>>>(att_W1, att_b1, p);
        k_attn<<<dim3(T, H * B), 128>>>(att_W2);
        k_mlp <<<BT / 2, 64>>>(proj_W, proj_b, ln2_g, ln2_b,
                               ff_W1, ff_b1, ff_W2, ff_b2, ln3_g, ln3_b,
                               ln1_g, ln1_b, val_W);
    }
    k_lm<<<dim3(V / 256, BT / 32), 64>>>(lm_W, lm_b, out);
}

// round 7
// speedup vs baseline: 1.5620x; 1.2732x over previous
#include <cuda_runtime.h>

#define DINL __device__ __forceinline__
typedef unsigned long long ull;
#define FULLM 0xffffffffu

constexpr int V   = 32000;
constexpr int C   = 64;
constexpr int H   = 4;
constexpr int S   = 16;
constexpr int T   = 128;
constexpr int B   = 2;
constexpr int HID = 256;
constexpr int NPE = 4;
constexpr int BT  = B * T;     // 256
constexpr int D4  = 4 * C;     // 256

// ---------------- scratch (device globals; no malloc allowed) ----------------
__device__ float g_x   [BT * C];
__device__ float g_xn  [BT * C];
__device__ float g_pos [NPE * T * C];
__device__ float g_Qh  [H * B * T * D4];   // 0.5*(Qp + b1), [hb][t][d]
__device__ float g_KhT [H * B * D4 * T];   // 0.5*Kp, transposed [hb][d][t]
__device__ float g_v   [H * B * T * S];    // [hb][t][s]
__device__ float g_o   [BT * C];

DINL float sigmoidf_(float x) { return 1.0f / (1.0f + __expf(-x)); }

// packed f32x2 helpers (Blackwell: fma.rn.f32x2)
DINL ull fma2_(ull a, ull b, ull c) {
    ull r;
    asm("fma.rn.f32x2 %0, %1, %2, %3;" : "=l"(r) : "l"(a), "l"(b), "l"(c));
    return r;
}
DINL ull pack2_(float v) {
    ull r; unsigned u = __float_as_uint(v);
    asm("mov.b64 %0, {%1, %2};" : "=l"(r) : "r"(u), "r"(u));
    return r;
}
DINL ull packlh_(float lo, float hi) {
    ull r;
    asm("mov.b64 %0, {%1, %2};" : "=l"(r) : "r"(__float_as_uint(lo)), "r"(__float_as_uint(hi)));
    return r;
}
DINL void unpack2_(ull v, float& lo, float& hi) {
    unsigned a, b;
    asm("mov.b64 {%0, %1}, %2;" : "=r"(a), "=r"(b) : "l"(v));
    lo = __uint_as_float(a); hi = __uint_as_float(b);
}
DINL float wsum32_(float v) {
#pragma unroll
    for (int off = 16; off; off >>= 1) v += __shfl_xor_sync(FULLM, v, off);
    return v;
}

// block-wide sum over exactly 64 threads
DINL float bsum64(float v, float* sb, int tid) {
    sb[tid] = v; __syncthreads();
#pragma unroll
    for (int off = 32; off; off >>= 1) {
        if (tid < off) sb[tid] += sb[tid + off];
        __syncthreads();
    }
    float r = sb[0]; __syncthreads();
    return r;
}

// ---------------- K0: positional embeddings (4 tables, table->FFN->LN) -------
__global__ void k_pos(const float* __restrict__ tab,
                      const float* __restrict__ W1, const float* __restrict__ b1,
                      const float* __restrict__ W2, const float* __restrict__ b2,
                      const float* __restrict__ lg, const float* __restrict__ lb) {
    int p = blockIdx.x, t = blockIdx.y, c = threadIdx.x;
    __shared__ float pe[64], hh[64], sb[64];
    pe[c] = tab[(p * T + t) * C + c];
    __syncthreads();
    float a = b1[p * C + c];
    const float* w1 = W1 + p * C * C;
#pragma unroll 8
    for (int k = 0; k < C; k++) a = fmaf(pe[k], w1[k * C + c], a);
    hh[c] = sigmoidf_(a);
    __syncthreads();
    float y = b2[p * C + c];
    const float* w2 = W2 + p * C * C;
#pragma unroll 8
    for (int k = 0; k < C; k++) y = fmaf(hh[k], w2[k * C + c], y);
    float m = bsum64(y, sb, c) * (1.f / C);
    float d = y - m;
    float var = bsum64(d * d, sb, c) * (1.f / C);
    g_pos[(p * T + t) * C + c] = d * rsqrtf(var + 1e-5f) * lg[p * C + c] + lb[p * C + c];
}

// ---------------- K1: embed gather + ln1 + v projection (first iter only) ----
__global__ void k_embln(const int* __restrict__ idxp, const float* __restrict__ tok,
                        const float* __restrict__ g1, const float* __restrict__ b1,
                        const float* __restrict__ valW) {
    int row = blockIdx.x, c = threadIdx.x;
    int b = row >> 7, t = row & 127;
    __shared__ float xs[64], sb[64];
    float x = tok[idxp[row] * C + c];
    g_x[row * C + c] = x;
    float m = bsum64(x, sb, c) * (1.f / C);
    float d = x - m;
    float var = bsum64(d * d, sb, c) * (1.f / C);
    float xn = d * rsqrtf(var + 1e-5f) * g1[c] + b1[c];
    g_xn[row * C + c] = xn;
    xs[c] = xn;
    __syncthreads();
    int h = c >> 4, s = c & 15;
    float a = 0.f;
    const float* w = valW + h * C * S + s;
#pragma unroll 8
    for (int k = 0; k < C; k++) a = fmaf(xs[k], w[k * S], a);
    g_v[((h * B + b) * T + t) * S + s] = a;
}

// ---------------- K2: Q/K projections, chunked register loads, f32x2 ---------
// grid (T/16, H*B, 4 d-quarters), block 64 (one thread per d within quarter)
__global__ void __launch_bounds__(64) k_qk(const float* __restrict__ W1,
                                           const float* __restrict__ b1, int p) {
    int dq = blockIdx.z;
    int hb = blockIdx.y;
    int h = hb >> 1, b = hb & 1;
    int t0 = blockIdx.x * 16;
    int tid = threadIdx.x;              // 0..63
    int d = dq * 64 + tid;

    __shared__ float xs[128][18];       // [c][tt], 16 tokens, 8B-aligned rows

    for (int idx = tid; idx < 128 * 16; idx += 64) {
        int c = idx & 127, tt = idx >> 7;
        xs[c][tt] = (c < 64) ? g_pos[(p * T + t0 + tt) * C + c]
                             : g_xn[(b * T + t0 + tt) * C + (c - 64)];
    }
    __syncthreads();

    ull ak2[8], aq2[8];
    ull bq2 = pack2_(0.5f * b1[h * D4 + d]);
#pragma unroll
    for (int u = 0; u < 8; u++) { ak2[u] = 0ULL; aq2[u] = bq2; }

    const float* Wk = W1 + h * D4 * D4 + d;   // rows [0,128): key half
    const float* Wq = Wk + 128 * D4;          // rows [128,256): query half

    for (int c0 = 0; c0 < 128; c0 += 16) {
        float wk[16], wq[16];
#pragma unroll
        for (int u = 0; u < 16; u++) {
            wk[u] = Wk[(c0 + u) * D4];
            wq[u] = Wq[(c0 + u) * D4];
        }
#pragma unroll
        for (int cc = 0; cc < 16; cc++) {
            ull wk2 = pack2_(0.5f * wk[cc]);
            ull wq2 = pack2_(0.5f * wq[cc]);
            const ull* xp = reinterpret_cast<const ull*>(&xs[c0 + cc][0]);
#pragma unroll
            for (int u = 0; u < 8; u++) {
                ull xv = xp[u];
                ak2[u] = fma2_(xv, wk2, ak2[u]);
                aq2[u] = fma2_(xv, wq2, aq2[u]);
            }
        }
    }

    // K transposed: thread owns row d, writes 16 consecutive t as 8B pairs
    float* kout = &g_KhT[(hb * D4 + d) * T + t0];
#pragma unroll
    for (int u = 0; u < 8; u++)
        *reinterpret_cast<ull*>(&kout[2 * u]) = ak2[u];
    // Q: scatter per t (coalesced across tid)
#pragma unroll
    for (int u = 0; u < 8; u++) {
        float lo, hi; unpack2_(aq2[u], lo, hi);
        g_Qh[(hb * T + t0 + 2 * u) * D4 + d]     = lo;
        g_Qh[(hb * T + t0 + 2 * u + 1) * D4 + d] = hi;
    }
}

// ---------------- K3: scores (tanh trick) + softmax + o -----------------------
__global__ void k_attn(const float* __restrict__ W2a) {
    int i = blockIdx.x, hb = blockIdx.y;
    int h = hb >> 1, b = hb & 1;
    int j = threadIdx.x;  // 0..127
    __shared__ float2 qw[256];
    __shared__ float wei[128], rb[128];
    qw[j]       = make_float2(g_Qh[(hb * T + i) * D4 + j],
                              0.5f * W2a[h * D4 + j]);
    qw[128 + j] = make_float2(g_Qh[(hb * T + i) * D4 + 128 + j],
                              0.5f * W2a[h * D4 + 128 + j]);
    __syncthreads();
    float sc = -1e30f;
    if (j <= i) {
        const float* Kc = g_KhT + hb * D4 * T + j;
        float acc = 0.f;
        for (int d0 = 0; d0 < D4; d0 += 16) {
            float kb[16];
#pragma unroll
            for (int u = 0; u < 16; u++) kb[u] = Kc[(d0 + u) * T];
#pragma unroll
            for (int u = 0; u < 16; u++) {
                float2 q = qw[d0 + u];
                float th;
                asm("tanh.approx.f32 %0, %1;" : "=f"(th) : "f"(q.x + kb[u]));
                acc = fmaf(q.y, th, acc);
            }
        }
        sc = acc * 0.125f;  // C^-0.5; constant terms cancel in softmax
    }
    // softmax over j in [0, i]
    rb[j] = sc; __syncthreads();
#pragma unroll
    for (int off = 64; off; off >>= 1) {
        if (j < off) rb[j] = fmaxf(rb[j], rb[j + off]);
        __syncthreads();
    }
    float mx = rb[0]; __syncthreads();
    float w = (j <= i) ? __expf(sc - mx) : 0.f;
    rb[j] = w; __syncthreads();
#pragma unroll
    for (int off = 64; off; off >>= 1) {
        if (j < off) rb[j] += rb[j + off];
        __syncthreads();
    }
    float ssum = rb[0]; __syncthreads();
    wei[j] = w * __fdividef(1.f, ssum);
    __syncthreads();
    // o[i, h*16+s] = sum_j wei[j] * v[j][s]
    int so = j & 15, part = j >> 4;
    const float* vp = g_v + hb * T * S;
    float a = 0.f;
    for (int jj = part; jj <= i; jj += 8) a = fmaf(wei[jj], vp[jj * S + so], a);
    rb[j] = a; __syncthreads();
    if (j < 16) {
#pragma unroll
        for (int k = 1; k < 8; k++) a += rb[k * 16 + j];
        g_o[(b * T + i) * C + h * S + j] = a;
    }
}

// ---------------- K4: warp-per-row proj+ln2+FFN+ln3, fused ln1+v --------------
// grid(BT/2) x 64 threads: each warp owns one row; no __syncthreads.
__global__ void __launch_bounds__(64) k_mlp(
        const float* __restrict__ pW, const float* __restrict__ pb,
        const float* __restrict__ g2, const float* __restrict__ b2,
        const float* __restrict__ fW1, const float* __restrict__ fb1,
        const float* __restrict__ fW2, const float* __restrict__ fb2,
        const float* __restrict__ g3, const float* __restrict__ b3,
        const float* __restrict__ g1, const float* __restrict__ b1,
        const float* __restrict__ valW) {
    int w = threadIdx.x >> 5, lam = threadIdx.x & 31;
    int row = blockIdx.x * 2 + w;
    int b = row >> 7, t = row & 127;
    __shared__ ull hs2[2][256];

    float2 o2 = reinterpret_cast<const float2*>(g_o)[row * 32 + lam];
    float2 x2 = reinterpret_cast<const float2*>(g_x)[row * 32 + lam];
    float2 pb2 = reinterpret_cast<const float2*>(pb)[lam];

    // proj + residual: acc = x + pb + o @ pW
    ull acc = packlh_(x2.x + pb2.x, x2.y + pb2.y);
    const ull* pW2 = reinterpret_cast<const ull*>(pW);
#pragma unroll 4
    for (int kp = 0; kp < 32; kp++) {
        float ox = __shfl_sync(FULLM, o2.x, kp);
        float oy = __shfl_sync(FULLM, o2.y, kp);
        ull w0 = pW2[(2 * kp) * 32 + lam];
        ull w1 = pW2[(2 * kp + 1) * 32 + lam];
        acc = fma2_(pack2_(ox), w0, acc);
        acc = fma2_(pack2_(oy), w1, acc);
    }
    float xv0, xv1; unpack2_(acc, xv0, xv1);

    // ln2
    float m = wsum32_(xv0 + xv1) * (1.f / C);
    float d0 = xv0 - m, d1 = xv1 - m;
    float var = wsum32_(d0 * d0 + d1 * d1) * (1.f / C);
    float rstd = rsqrtf(var + 1e-5f);
    float2 g2v = reinterpret_cast<const float2*>(g2)[lam];
    float2 b2v = reinterpret_cast<const float2*>(b2)[lam];
    float xn0 = d0 * rstd * g2v.x + b2v.x;
    float xn1 = d1 * rstd * g2v.y + b2v.y;

    // FFN1: lane owns hid [8*lam, 8*lam+8)
    ull a4[4];
    const ull* fb1u = reinterpret_cast<const ull*>(fb1);
#pragma unroll
    for (int u = 0; u < 4; u++) a4[u] = fb1u[lam * 4 + u];
#pragma unroll 4
    for (int kp = 0; kp < 32; kp++) {
        float k0v = __shfl_sync(FULLM, xn0, kp);
        float k1v = __shfl_sync(FULLM, xn1, kp);
        const ull* r0 = reinterpret_cast<const ull*>(fW1 + (2 * kp) * HID) + lam * 4;
        const ull* r1 = r0 + HID / 2;
        ull p0 = pack2_(k0v), p1 = pack2_(k1v);
#pragma unroll
        for (int u = 0; u < 4; u++) {
            a4[u] = fma2_(p0, r0[u], a4[u]);
            a4[u] = fma2_(p1, r1[u], a4[u]);
        }
    }
#pragma unroll
    for (int u = 0; u < 4; u++) {
        float lo, hi; unpack2_(a4[u], lo, hi);
        hs2[w][8 * lam + 2 * u]     = pack2_(sigmoidf_(lo));
        hs2[w][8 * lam + 2 * u + 1] = pack2_(sigmoidf_(hi));
    }
    __syncwarp();

    // FFN2 + residual
    float2 fb2v = reinterpret_cast<const float2*>(fb2)[lam];
    ull accy = packlh_(xv0 + fb2v.x, xv1 + fb2v.y);
    const ull* fW2u = reinterpret_cast<const ull*>(fW2);
#pragma unroll 8
    for (int k = 0; k < HID; k++)
        accy = fma2_(hs2[w][k], fW2u[k * 32 + lam], accy);
    float y0, y1; unpack2_(accy, y0, y1);

    // ln3 -> block output
    m = wsum32_(y0 + y1) * (1.f / C);
    d0 = y0 - m; d1 = y1 - m;
    var = wsum32_(d0 * d0 + d1 * d1) * (1.f / C);
    rstd = rsqrtf(var + 1e-5f);
    float2 g3v = reinterpret_cast<const float2*>(g3)[lam];
    float2 b3v = reinterpret_cast<const float2*>(b3)[lam];
    float z0 = d0 * rstd * g3v.x + b3v.x;
    float z1 = d1 * rstd * g3v.y + b3v.y;
    reinterpret_cast<float2*>(g_x)[row * 32 + lam] = make_float2(z0, z1);

    // fused ln1 for next layer
    m = wsum32_(z0 + z1) * (1.f / C);
    d0 = z0 - m; d1 = z1 - m;
    var = wsum32_(d0 * d0 + d1 * d1) * (1.f / C);
    rstd = rsqrtf(var + 1e-5f);
    float2 g1v = reinterpret_cast<const float2*>(g1)[lam];
    float2 b1v = reinterpret_cast<const float2*>(b1)[lam];
    float q0 = d0 * rstd * g1v.x + b1v.x;
    float q1 = d1 * rstd * g1v.y + b1v.y;
    reinterpret_cast<float2*>(g_xn)[row * 32 + lam] = make_float2(q0, q1);

    // fused v projection: lane owns out pair c=(2lam, 2lam+1) -> h=lam>>3
    int hv = lam >> 3, sp = lam & 7;
    const ull* vwb = reinterpret_cast<const ull*>(valW) + hv * 512 + sp;
    ull accv = 0ULL;
#pragma unroll 4
    for (int kp = 0; kp < 32; kp++) {
        float k0v = __shfl_sync(FULLM, q0, kp);
        float k1v = __shfl_sync(FULLM, q1, kp);
        ull w0 = vwb[kp * 16];
        ull w1 = vwb[kp * 16 + 8];
        accv = fma2_(pack2_(k0v), w0, accv);
        accv = fma2_(pack2_(k1v), w1, accv);
    }
    reinterpret_cast<ull*>(g_v)[((hv * B + b) * T + t) * 8 + sp] = accv;
}

// ---------------- K5: lm_head, 4 vocab/thread, f32x2 --------------------------
// grid (V/256, BT/32), block 64; thread owns 2 vocab pairs, 32 rows.
__global__ void __launch_bounds__(64) k_lm(const float* __restrict__ W,
                                           const float* __restrict__ bias,
                                           float* __restrict__ out) {
    int vt = blockIdx.x, rt = blockIdx.y;
    int vv = vt * 256 + threadIdx.x * 4;
    __shared__ alignas(16) float xs[32][68];
    for (int idx = threadIdx.x; idx < 32 * 64; idx += 64) {
        int r = idx >> 6, cc = idx & 63;
        xs[r][cc] = g_x[(rt * 32 + r) * C + cc];
    }
    ulonglong2 bb = *reinterpret_cast<const ulonglong2*>(bias + vv);
    ull acc[32][2];
#pragma unroll
    for (int r = 0; r < 32; r++) { acc[r][0] = bb.x; acc[r][1] = bb.y; }
    __syncthreads();
    for (int cb = 0; cb < 64; cb += 4) {
        const ulonglong2 w0 = *reinterpret_cast<const ulonglong2*>(W + (size_t)(cb + 0) * V + vv);
        const ulonglong2 w1 = *reinterpret_cast<const ulonglong2*>(W + (size_t)(cb + 1) * V + vv);
        const ulonglong2 w2 = *reinterpret_cast<const ulonglong2*>(W + (size_t)(cb + 2) * V + vv);
        const ulonglong2 w3 = *reinterpret_cast<const ulonglong2*>(W + (size_t)(cb + 3) * V + vv);
#pragma unroll
        for (int r = 0; r < 32; r++) {
            const float4 xq = *reinterpret_cast<const float4*>(&xs[r][cb]);
            ull px;
            px = pack2_(xq.x); acc[r][0] = fma2_(w0.x, px, acc[r][0]); acc[r][1] = fma2_(w0.y, px, acc[r][1]);
            px = pack2_(xq.y); acc[r][0] = fma2_(w1.x, px, acc[r][0]); acc[r][1] = fma2_(w1.y, px, acc[r][1]);
            px = pack2_(xq.z); acc[r][0] = fma2_(w2.x, px, acc[r][0]); acc[r][1] = fma2_(w2.y, px, acc[r][1]);
            px = pack2_(xq.w); acc[r][0] = fma2_(w3.x, px, acc[r][0]); acc[r][1] = fma2_(w3.y, px, acc[r][1]);
        }
    }
#pragma unroll
    for (int r = 0; r < 32; r++) {
        ulonglong2 o2; o2.x = acc[r][0]; o2.y = acc[r][1];
        *reinterpret_cast<ulonglong2*>(out + (size_t)(rt * 32 + r) * V + vv) = o2;
    }
}

// ---------------- launch -------------------------------------------------------
extern "C" void kernel_launch(void* const* d_in, const int* in_sizes, int n_in,
                              void* d_out, int out_size) {
    (void)in_sizes; (void)n_in; (void)out_size;
    const int*   idx      = (const int*)  d_in[0];
    const float* tok_emb  = (const float*)d_in[1];
    const float* pe_tab   = (const float*)d_in[2];
    const float* pe_W1    = (const float*)d_in[3];
    const float* pe_b1    = (const float*)d_in[4];
    const float* pe_W2    = (const float*)d_in[5];
    const float* pe_b2    = (const float*)d_in[6];
    const float* pe_lg    = (const float*)d_in[7];
    const float* pe_lb    = (const float*)d_in[8];
    const float* ln1_g    = (const float*)d_in[9];
    const float* ln1_b    = (const float*)d_in[10];
    const float* att_W1   = (const float*)d_in[11];
    const float* att_b1   = (const float*)d_in[12];
    const float* att_W2   = (const float*)d_in[13];
    /* att_b2 = d_in[14] — constant over j, cancels in softmax */
    const float* val_W    = (const float*)d_in[15];
    const float* proj_W   = (const float*)d_in[16];
    const float* proj_b   = (const float*)d_in[17];
    const float* ln2_g    = (const float*)d_in[18];
    const float* ln2_b    = (const float*)d_in[19];
    const float* ff_W1    = (const float*)d_in[20];
    const float* ff_b1    = (const float*)d_in[21];
    const float* ff_W2    = (const float*)d_in[22];
    const float* ff_b2    = (const float*)d_in[23];
    const float* ln3_g    = (const float*)d_in[24];
    const float* ln3_b    = (const float*)d_in[25];
    const float* lm_W     = (const float*)d_in[26];
    const float* lm_b     = (const float*)d_in[27];
    float* out = (float*)d_out;

    k_pos<<<dim3(NPE, T), 64>>>(pe_tab, pe_W1, pe_b1, pe_W2, pe_b2, pe_lg, pe_lb);
    k_embln<<<BT, 64>>>(idx, tok_emb, ln1_g, ln1_b, val_W);
    for (int p = 0; p < NPE; p++) {
        k_qk  <<<dim3(T / 16, H * B, 4), 64>>>(att_W1, att_b1, p);
        k_attn<<<dim3(T, H * B), 128>>>(att_W2);
        k_mlp <<<BT / 2, 64>>>(proj_W, proj_b, ln2_g, ln2_b,
                               ff_W1, ff_b1, ff_W2, ff_b2, ln3_g, ln3_b,
                               ln1_g, ln1_b, val_W);
    }
    k_lm<<<dim3(V / 256, BT / 32), 64>>>(lm_W, lm_b, out);
}